// round 7
// baseline (speedup 1.0000x reference)
#include <cuda_runtime.h>
#include <cuda_bf16.h>
#include <cstdint>

// EdgeConvE: B=4, V=1024, C=64, E=16, K=32, OUT=128, NODES=4096, EDGES=131072
// src = repeat(arange(4096), 32) (structural) => segment n = edges [n*32,(n+1)*32)
// dst & 1023 = local neighbor (block-diagonal graphs).
//
// Algebra: feat@W = x_s@(W1-W2) + x_d@W2 + e@W3
//   A[n] = x_n@(W1-W2)+b ; C[n] = x_n@W2
//   out[n][j] = max(0, A[n][j] + max_k( C[dst_k][j] + e_k . W3[:,j] ))

#define NODES 4096
#define VDIM  1024
#define CDIM  64
#define EDIM  16
#define KNBR  32
#define OUTD  128

__device__ float g_A[NODES * OUTD];
__device__ float g_C[NODES * OUTD];

// ---------------- f32x2 helpers ----------------
__device__ __forceinline__ uint64_t pack_f32x2(float lo, float hi) {
    uint64_t r;
    asm("mov.b64 %0, {%1, %2};" : "=l"(r) : "f"(lo), "f"(hi));
    return r;
}
__device__ __forceinline__ void unpack_f32x2(float& lo, float& hi, uint64_t v) {
    asm("mov.b64 {%0, %1}, %2;" : "=f"(lo), "=f"(hi) : "l"(v));
}
__device__ __forceinline__ uint64_t fma_f32x2(uint64_t a, uint64_t b, uint64_t c) {
    uint64_t d;
    asm("fma.rn.f32x2 %0, %1, %2, %3;" : "=l"(d) : "l"(a), "l"(b), "l"(c));
    return d;
}
__device__ __forceinline__ void lds_v2_u64(uint64_t& a, uint64_t& b, uint32_t addr) {
    asm("ld.shared.v2.u64 {%0, %1}, [%2];" : "=l"(a), "=l"(b) : "r"(addr));
}
__device__ __forceinline__ uint64_t lds_u64(uint32_t addr) {
    uint64_t a;
    asm("ld.shared.u64 %0, [%1];" : "=l"(a) : "r"(addr));
    return a;
}
__device__ __forceinline__ uint32_t smem_u32(const void* p) {
    return (uint32_t)__cvta_generic_to_shared(p);
}
__device__ __forceinline__ void cp_async16(uint32_t s, const void* g) {
    asm volatile("cp.async.cg.shared.global [%0], [%1], 16;" :: "r"(s), "l"(g));
}

// ---------------------------------------------------------------------------
// Kernel 1: per-node linear tables (f32x2-packed over node pairs). grid 512.
// ---------------------------------------------------------------------------
#define NT_NODES 8
__global__ void __launch_bounds__(128) node_tables_kernel(
    const float* __restrict__ x, const float* __restrict__ W,
    const float* __restrict__ bias)
{
    __shared__ float xs[CDIM][NT_NODES];
    const int j  = threadIdx.x;
    const int n0 = blockIdx.x * NT_NODES;

    for (int it = 0; it < NT_NODES * CDIM / 128; it++) {
        int idx = j + it * 128;
        xs[idx & 63][idx >> 6] = x[n0 * CDIM + idx];
    }
    __syncthreads();

    const float bj = bias[j];
    uint64_t accA[NT_NODES / 2], accC[NT_NODES / 2];
#pragma unroll
    for (int p = 0; p < NT_NODES / 2; p++) {
        accA[p] = pack_f32x2(bj, bj);
        accC[p] = pack_f32x2(0.0f, 0.0f);
    }
    const uint32_t xs_base = smem_u32(&xs[0][0]);

#pragma unroll 8
    for (int c = 0; c < CDIM; c++) {
        const float w1 = W[c * OUTD + j];
        const float w2 = W[(CDIM + c) * OUTD + j];
        const uint64_t wd2 = pack_f32x2(w1 - w2, w1 - w2);
        const uint64_t w22 = pack_f32x2(w2, w2);
        const uint32_t rowa = xs_base + c * (NT_NODES * 4);
#pragma unroll
        for (int p = 0; p < NT_NODES / 2; p++) {
            uint64_t xv2 = lds_u64(rowa + p * 8);
            accA[p] = fma_f32x2(xv2, wd2, accA[p]);
            accC[p] = fma_f32x2(xv2, w22, accC[p]);
        }
    }
#pragma unroll
    for (int p = 0; p < NT_NODES / 2; p++) {
        float a0, a1, c0, c1;
        unpack_f32x2(a0, a1, accA[p]);
        unpack_f32x2(c0, c1, accC[p]);
        g_A[(n0 + 2 * p) * OUTD + j]     = a0;
        g_A[(n0 + 2 * p + 1) * OUTD + j] = a1;
        g_C[(n0 + 2 * p) * OUTD + j]     = c0;
        g_C[(n0 + 2 * p + 1) * OUTD + j] = c1;
    }
}

// ---------------------------------------------------------------------------
// Kernel 2: ONE node per 64-thread block, grid 4096 (~2.5 waves).
//   thread t owns cols (2t, 2t+1), iterates all 32 k.
//   Inter-BLOCK overlap hides the gather/L2 latencies: late blocks' DRAM
//   gathers stream while early blocks compute.
// ---------------------------------------------------------------------------
__global__ void __launch_bounds__(64) edge_max_kernel(
    const float* __restrict__ eattr,  // [4,1024,1024,16]
    const float* __restrict__ W,      // [144,128]
    const int*   __restrict__ dst,    // [131072]
    float*       __restrict__ out)    // [4096,128]
{
    const int n  = blockIdx.x;
    const int t  = threadIdx.x;       // 0..63
    const int j0 = t * 2;

    __shared__ int sd[KNBR];
    __shared__ __align__(16) float se[KNBR][EDIM];   // 2 KB

    if (t < KNBR) sd[t] = dst[n * KNBR + t];
    __syncthreads();

    // 128 gather chunks (32 rows x 4 x 16B), 2 per thread
#pragma unroll
    for (int half = 0; half < 2; half++) {
        const int c  = t + half * 64;
        const int ck = c >> 2;
        const int cq = c & 3;
        const int ui = sd[ck] & (VDIM - 1);
        cp_async16(smem_u32(&se[ck][cq * 4]),
                   eattr + ((size_t)n * VDIM + ui) * EDIM + cq * 4);
    }
    asm volatile("cp.async.commit_group;");

    // W3 t-pair columns for cols j0, j0+1 (overlaps with gather DRAM time)
    uint64_t w3a[8], w3b[8];
#pragma unroll
    for (int p = 0; p < 8; p++) {
        w3a[p] = pack_f32x2(W[(2 * CDIM + 2 * p) * OUTD + j0],
                            W[(2 * CDIM + 2 * p + 1) * OUTD + j0]);
        w3b[p] = pack_f32x2(W[(2 * CDIM + 2 * p) * OUTD + j0 + 1],
                            W[(2 * CDIM + 2 * p + 1) * OUTD + j0 + 1]);
    }
    const float2 av = *reinterpret_cast<const float2*>(g_A + n * OUTD + j0);

    asm volatile("cp.async.wait_group 0;");
    __syncthreads();

    const uint32_t se_base = smem_u32(&se[0][0]);
    float best0 = -1e30f, best1 = -1e30f;

#pragma unroll
    for (int kb = 0; kb < KNBR; kb += 8) {
        // C-table rows for this chunk (L2-resident; stall covered by other blocks)
        float2 cv[8];
#pragma unroll
        for (int u = 0; u < 8; u++)
            cv[u] = *reinterpret_cast<const float2*>(g_C + sd[kb + u] * OUTD + j0);

#pragma unroll
        for (int u = 0; u < 8; u++) {
            const uint32_t row = se_base + (kb + u) * (EDIM * 4);
            uint64_t e0, e1, e2, e3, e4, e5, e6, e7;
            lds_v2_u64(e0, e1, row);
            lds_v2_u64(e2, e3, row + 16);
            lds_v2_u64(e4, e5, row + 32);
            lds_v2_u64(e6, e7, row + 48);

            uint64_t a0 = pack_f32x2(cv[u].x, 0.0f);
            uint64_t a1 = pack_f32x2(cv[u].y, 0.0f);
            a0 = fma_f32x2(e0, w3a[0], a0);  a1 = fma_f32x2(e0, w3b[0], a1);
            a0 = fma_f32x2(e1, w3a[1], a0);  a1 = fma_f32x2(e1, w3b[1], a1);
            a0 = fma_f32x2(e2, w3a[2], a0);  a1 = fma_f32x2(e2, w3b[2], a1);
            a0 = fma_f32x2(e3, w3a[3], a0);  a1 = fma_f32x2(e3, w3b[3], a1);
            a0 = fma_f32x2(e4, w3a[4], a0);  a1 = fma_f32x2(e4, w3b[4], a1);
            a0 = fma_f32x2(e5, w3a[5], a0);  a1 = fma_f32x2(e5, w3b[5], a1);
            a0 = fma_f32x2(e6, w3a[6], a0);  a1 = fma_f32x2(e6, w3b[6], a1);
            a0 = fma_f32x2(e7, w3a[7], a0);  a1 = fma_f32x2(e7, w3b[7], a1);

            float lo0, hi0, lo1, hi1;
            unpack_f32x2(lo0, hi0, a0);
            unpack_f32x2(lo1, hi1, a1);
            best0 = fmaxf(best0, lo0 + hi0);
            best1 = fmaxf(best1, lo1 + hi1);
        }
    }

    float r0 = fmaxf(av.x + best0, 0.0f);
    float r1 = fmaxf(av.y + best1, 0.0f);
    *reinterpret_cast<float2*>(out + n * OUTD + j0) = make_float2(r0, r1);
}

// ---------------------------------------------------------------------------
// Inputs: 0 node_features [4,1024,64] f32 | 1 edge_attributes [4,1024,1024,16] f32
//         2 W [144,128] f32 | 3 b [128] f32 | 4 src i32 (unused) | 5 dst i32
// Output: f32 [4,1024,128]
// ---------------------------------------------------------------------------
extern "C" void kernel_launch(void* const* d_in, const int* in_sizes, int n_in,
                              void* d_out, int out_size)
{
    const float* x     = (const float*)d_in[0];
    const float* eattr = (const float*)d_in[1];
    const float* W     = (const float*)d_in[2];
    const float* bias  = (const float*)d_in[3];
    const int*   dst   = (const int*)d_in[5];
    float*       out   = (float*)d_out;

    node_tables_kernel<<<NODES / NT_NODES, 128>>>(x, W, bias);
    edge_max_kernel<<<NODES, 64>>>(eattr, W, dst, out);
}

// round 8
// speedup vs baseline: 1.0110x; 1.0110x over previous
#include <cuda_runtime.h>
#include <cuda_bf16.h>
#include <cstdint>

// EdgeConvE: B=4, V=1024, C=64, E=16, K=32, OUT=128, NODES=4096, EDGES=131072
// src = repeat(arange(4096), 32) (structural) => segment n = edges [n*32,(n+1)*32)
// dst & 1023 = local neighbor (block-diagonal graphs).
//
// Algebra: feat@W = x_s@(W1-W2) + x_d@W2 + e@W3
//   A[n] = x_n@(W1-W2)+b ; C[n] = x_n@W2
//   out[n][j] = max(0, A[n][j] + max_k( C[dst_k][j] + (e_k . W3[:,j]) ))
// e@W3 done with mma.sync.m16n8k8 tf32 (3xTF32 split -> fp32-level accuracy).

#define NODES 4096
#define VDIM  1024
#define CDIM  64
#define EDIM  16
#define KNBR  32
#define OUTD  128
#define ENPB  2          // nodes per block in edge kernel
#define EPAD  20         // E smem row stride in floats (bank-conflict-free)

__device__ float g_A[NODES * OUTD];
__device__ float g_C[NODES * OUTD];

// ---------------- helpers ----------------
__device__ __forceinline__ uint64_t pack_f32x2(float lo, float hi) {
    uint64_t r;
    asm("mov.b64 %0, {%1, %2};" : "=l"(r) : "f"(lo), "f"(hi));
    return r;
}
__device__ __forceinline__ void unpack_f32x2(float& lo, float& hi, uint64_t v) {
    asm("mov.b64 {%0, %1}, %2;" : "=f"(lo), "=f"(hi) : "l"(v));
}
__device__ __forceinline__ uint64_t fma_f32x2(uint64_t a, uint64_t b, uint64_t c) {
    uint64_t d;
    asm("fma.rn.f32x2 %0, %1, %2, %3;" : "=l"(d) : "l"(a), "l"(b), "l"(c));
    return d;
}
__device__ __forceinline__ uint64_t lds_u64(uint32_t addr) {
    uint64_t a;
    asm("ld.shared.u64 %0, [%1];" : "=l"(a) : "r"(addr));
    return a;
}
__device__ __forceinline__ uint32_t smem_u32(const void* p) {
    return (uint32_t)__cvta_generic_to_shared(p);
}
__device__ __forceinline__ void cp_async16(uint32_t s, const void* g) {
    asm volatile("cp.async.cg.shared.global [%0], [%1], 16;" :: "r"(s), "l"(g));
}
__device__ __forceinline__ uint32_t f2tf32(float f) {
    uint32_t u;
    asm("cvt.rna.tf32.f32 %0, %1;" : "=r"(u) : "f"(f));
    return u;
}
// D += A(tf32 m16k8 row) * B(tf32 k8n8 col)
__device__ __forceinline__ void mma_tf32(float* c, const uint32_t* a, const uint32_t* b) {
    asm volatile(
        "mma.sync.aligned.m16n8k8.row.col.f32.tf32.tf32.f32 "
        "{%0,%1,%2,%3}, {%4,%5,%6,%7}, {%8,%9}, {%0,%1,%2,%3};"
        : "+f"(c[0]), "+f"(c[1]), "+f"(c[2]), "+f"(c[3])
        : "r"(a[0]), "r"(a[1]), "r"(a[2]), "r"(a[3]), "r"(b[0]), "r"(b[1]));
}

// ---------------------------------------------------------------------------
// Kernel 1: per-node linear tables (f32x2-packed over node pairs). grid 512.
// ---------------------------------------------------------------------------
#define NT_NODES 8
__global__ void __launch_bounds__(128) node_tables_kernel(
    const float* __restrict__ x, const float* __restrict__ W,
    const float* __restrict__ bias)
{
    __shared__ float xs[CDIM][NT_NODES];
    const int j  = threadIdx.x;
    const int n0 = blockIdx.x * NT_NODES;

    for (int it = 0; it < NT_NODES * CDIM / 128; it++) {
        int idx = j + it * 128;
        xs[idx & 63][idx >> 6] = x[n0 * CDIM + idx];
    }
    __syncthreads();

    const float bj = bias[j];
    uint64_t accA[NT_NODES / 2], accC[NT_NODES / 2];
#pragma unroll
    for (int p = 0; p < NT_NODES / 2; p++) {
        accA[p] = pack_f32x2(bj, bj);
        accC[p] = pack_f32x2(0.0f, 0.0f);
    }
    const uint32_t xs_base = smem_u32(&xs[0][0]);

#pragma unroll 8
    for (int c = 0; c < CDIM; c++) {
        const float w1 = W[c * OUTD + j];
        const float w2 = W[(CDIM + c) * OUTD + j];
        const uint64_t wd2 = pack_f32x2(w1 - w2, w1 - w2);
        const uint64_t w22 = pack_f32x2(w2, w2);
        const uint32_t rowa = xs_base + c * (NT_NODES * 4);
#pragma unroll
        for (int p = 0; p < NT_NODES / 2; p++) {
            uint64_t xv2 = lds_u64(rowa + p * 8);
            accA[p] = fma_f32x2(xv2, wd2, accA[p]);
            accC[p] = fma_f32x2(xv2, w22, accC[p]);
        }
    }
#pragma unroll
    for (int p = 0; p < NT_NODES / 2; p++) {
        float a0, a1, c0, c1;
        unpack_f32x2(a0, a1, accA[p]);
        unpack_f32x2(c0, c1, accC[p]);
        g_A[(n0 + 2 * p) * OUTD + j]     = a0;
        g_A[(n0 + 2 * p + 1) * OUTD + j] = a1;
        g_C[(n0 + 2 * p) * OUTD + j]     = c0;
        g_C[(n0 + 2 * p + 1) * OUTD + j] = c1;
    }
}

// ---------------------------------------------------------------------------
// Kernel 2: tensor-core edge kernel. 128 threads = 4 warps; warp w owns
// cols [32w,32w+32) of a node; 2 nodes per block (double-buffered cp.async).
// P[32x128] = E[32x16] @ W3[16x128] via m16n8k8 tf32 (3xTF32), then
// C[dst]-add + max over edges in accumulator layout + shfl reduction.
// ---------------------------------------------------------------------------
__global__ void __launch_bounds__(128) edge_max_kernel(
    const float* __restrict__ eattr,  // [4,1024,1024,16]
    const float* __restrict__ W,      // [144,128]
    const int*   __restrict__ dst,    // [131072]
    float*       __restrict__ out)    // [4096,128]
{
    const int t  = threadIdx.x;
    const int w  = t >> 5;
    const int l  = t & 31;
    const int g  = l >> 2;            // groupID (0..7)
    const int c4 = l & 3;             // threadID-in-group
    const int node0 = blockIdx.x * ENPB;

    __shared__ int sd[ENPB][KNBR];
    __shared__ __align__(16) float se[ENPB][KNBR][EPAD];

    // dst for both nodes: one coalesced 64-thread load
    if (t < ENPB * KNBR) sd[t >> 5][t & 31] = dst[node0 * KNBR + t];
    __syncthreads();

    // gather E rows for both nodes (128 16B-chunks each, 1/thread)
#pragma unroll
    for (int p = 0; p < ENPB; p++) {
        const int ck = t >> 2, cq = t & 3;
        const int ui = sd[p][ck] & (VDIM - 1);
        cp_async16(smem_u32(&se[p][ck][cq * 4]),
                   eattr + ((size_t)(node0 + p) * VDIM + ui) * EDIM + cq * 4);
        asm volatile("cp.async.commit_group;");
    }

    // B-frags: W3 cols [32w,32w+32) as 4 n-tiles x 2 k-tiles, hi/lo tf32 split
    uint32_t bhi[4][2][2], blo[4][2][2];
#pragma unroll
    for (int nt = 0; nt < 4; nt++) {
#pragma unroll
        for (int kt = 0; kt < 2; kt++) {
            const int col = 32 * w + 8 * nt + g;
            const float b0 = W[(2 * CDIM + 8 * kt + c4) * OUTD + col];
            const float b1 = W[(2 * CDIM + 8 * kt + c4 + 4) * OUTD + col];
            bhi[nt][kt][0] = f2tf32(b0);
            blo[nt][kt][0] = f2tf32(b0 - __uint_as_float(bhi[nt][kt][0]));
            bhi[nt][kt][1] = f2tf32(b1);
            blo[nt][kt][1] = f2tf32(b1 - __uint_as_float(bhi[nt][kt][1]));
        }
    }

#pragma unroll
    for (int p = 0; p < ENPB; p++) {
        if (p == 0) asm volatile("cp.async.wait_group 1;");
        else        asm volatile("cp.async.wait_group 0;");
        __syncthreads();

        const int n = node0 + p;
        float cm0[4], cm1[4];
#pragma unroll
        for (int nt = 0; nt < 4; nt++) { cm0[nt] = -1e30f; cm1[nt] = -1e30f; }

#pragma unroll
        for (int mt = 0; mt < 2; mt++) {
            // A-frags (E rows 16mt..16mt+15), conflict-free LDS, 3xTF32 split
            uint32_t ahi[2][4], alo[2][4];
#pragma unroll
            for (int kt = 0; kt < 2; kt++) {
                float af[4];
                af[0] = se[p][16 * mt + g][8 * kt + c4];
                af[1] = se[p][16 * mt + 8 + g][8 * kt + c4];
                af[2] = se[p][16 * mt + g][8 * kt + c4 + 4];
                af[3] = se[p][16 * mt + 8 + g][8 * kt + c4 + 4];
#pragma unroll
                for (int i = 0; i < 4; i++) {
                    ahi[kt][i] = f2tf32(af[i]);
                    alo[kt][i] = f2tf32(af[i] - __uint_as_float(ahi[kt][i]));
                }
            }
            const int dr0 = sd[p][16 * mt + g];
            const int dr1 = sd[p][16 * mt + 8 + g];

#pragma unroll
            for (int nt = 0; nt < 4; nt++) {
                float acc[4] = {0.0f, 0.0f, 0.0f, 0.0f};
#pragma unroll
                for (int kt = 0; kt < 2; kt++) {
                    mma_tf32(acc, ahi[kt], bhi[nt][kt]);
                    mma_tf32(acc, alo[kt], bhi[nt][kt]);
                    mma_tf32(acc, ahi[kt], blo[nt][kt]);
                }
                const int j0 = 32 * w + 8 * nt + 2 * c4;
                const float2 cv0 = *reinterpret_cast<const float2*>(g_C + dr0 * OUTD + j0);
                const float2 cv1 = *reinterpret_cast<const float2*>(g_C + dr1 * OUTD + j0);
                cm0[nt] = fmaxf(cm0[nt], fmaxf(acc[0] + cv0.x, acc[2] + cv1.x));
                cm1[nt] = fmaxf(cm1[nt], fmaxf(acc[1] + cv0.y, acc[3] + cv1.y));
            }
        }

        // max over the 8 lane-groups (rows), then add A + relu + store
#pragma unroll
        for (int nt = 0; nt < 4; nt++) {
            float v0 = cm0[nt], v1 = cm1[nt];
#pragma unroll
            for (int off = 4; off <= 16; off <<= 1) {
                v0 = fmaxf(v0, __shfl_xor_sync(0xffffffffu, v0, off));
                v1 = fmaxf(v1, __shfl_xor_sync(0xffffffffu, v1, off));
            }
            if (l < 4) {
                const int j0 = 32 * w + 8 * nt + 2 * l;
                const float2 av = *reinterpret_cast<const float2*>(g_A + n * OUTD + j0);
                float2 r;
                r.x = fmaxf(v0 + av.x, 0.0f);
                r.y = fmaxf(v1 + av.y, 0.0f);
                *reinterpret_cast<float2*>(out + n * OUTD + j0) = r;
            }
        }
    }
}

// ---------------------------------------------------------------------------
// Inputs: 0 node_features [4,1024,64] f32 | 1 edge_attributes [4,1024,1024,16] f32
//         2 W [144,128] f32 | 3 b [128] f32 | 4 src i32 (unused) | 5 dst i32
// Output: f32 [4,1024,128]
// ---------------------------------------------------------------------------
extern "C" void kernel_launch(void* const* d_in, const int* in_sizes, int n_in,
                              void* d_out, int out_size)
{
    const float* x     = (const float*)d_in[0];
    const float* eattr = (const float*)d_in[1];
    const float* W     = (const float*)d_in[2];
    const float* bias  = (const float*)d_in[3];
    const int*   dst   = (const int*)d_in[5];
    float*       out   = (float*)d_out;

    node_tables_kernel<<<NODES / NT_NODES, 128>>>(x, W, bias);
    edge_max_kernel<<<NODES / ENPB, 128>>>(eattr, W, dst, out);
}